// round 10
// baseline (speedup 1.0000x reference)
#include <cuda_runtime.h>
#include <math.h>

#define B 64
#define S 64
#define L 64
#define H 1024
#define CDIM 2048
#define E 512
#define OC (H + E + CDIM)   // 3584
#define XK (E + CDIM)       // 2560
#define G3 (3 * H)          // 3072
#define BH (B * H)
#define BG3 (B * G3)

#define NBLK 296
#define NTHR 256

// ---------------- scratch (device globals) ----------------------------------
__device__ float g_ctxproj[B * L * H];            // 16.8 MB
__device__ float g_giemb[(size_t)B * S * G3];     // 50.3 MB
__device__ float g_ctxW[(size_t)B * L * G3];      // 50.3 MB : ctx @ Wihc^T
__device__ float g_h[BH];
__device__ float g_hr[BH];
__device__ float g_score[B * L];
__device__ float g_qpart[8 * BH];
__device__ float g_ghpart[8 * (size_t)BG3];       // 6.3 MB
// pre-rounded weights / operands
__device__ float g_Wq[H * H];
__device__ float g_Whh[G3 * H];
__device__ float g_Wihc[(size_t)G3 * CDIM];
__device__ float g_Wihe[G3 * E];
__device__ float g_Wcr[H * CDIM];
__device__ float g_ctxr[B * L * CDIM];
__device__ float g_xemb[B * S * E];

// ---------------- grid barrier -------------------------------------------------
__device__ unsigned g_cnt;
__device__ volatile unsigned g_gen;

__device__ __forceinline__ void gsync() {
    __syncthreads();
    if (threadIdx.x == 0) {
        unsigned g = g_gen;
        __threadfence();                            // release my phase writes
        if (atomicAdd(&g_cnt, 1u) == NBLK - 1) {
            g_cnt = 0;
            __threadfence();
            g_gen = g + 1;
        } else {
            int spins = 0;
            while (g_gen == g) {
                if (++spins > 128) __nanosleep(64);
            }
        }
        __threadfence();                            // acquire: invalidate L1
    }
    __syncthreads();
}

// ---------------- helpers ----------------------------------------------------
__device__ __forceinline__ unsigned f2tf32(float x) {
    unsigned y;
    asm("cvt.rna.tf32.f32 %0, %1;" : "=r"(y) : "f"(x));
    return y;
}
__device__ __forceinline__ float round_tf32(float x) {
    return __uint_as_float(f2tf32(x));
}
__device__ __forceinline__ void mma_tf32(float* c, const unsigned* a, const unsigned* b) {
    asm volatile(
        "mma.sync.aligned.m16n8k8.row.col.f32.tf32.tf32.f32 "
        "{%0,%1,%2,%3},{%4,%5,%6,%7},{%8,%9},{%0,%1,%2,%3};"
        : "+f"(c[0]), "+f"(c[1]), "+f"(c[2]), "+f"(c[3])
        : "r"(a[0]), "r"(a[1]), "r"(a[2]), "r"(a[3]), "r"(b[0]), "r"(b[1]));
}
__device__ __forceinline__ void cp_async16(unsigned dst, const void* src) {
    asm volatile("cp.async.cg.shared.global [%0], [%1], 16;" :: "r"(dst), "l"(src));
}
__device__ __forceinline__ void cp_commit() {
    asm volatile("cp.async.commit_group;");
}
__device__ __forceinline__ void cp_wait1() {
    asm volatile("cp.async.wait_group 1;");
}
__device__ __forceinline__ void cp_wait0() {
    asm volatile("cp.async.wait_group 0;");
}

// ---------------- FFMA-only fast tanh ----------------------------------------
__device__ __forceinline__ float tanh_fast(float x) {
    float y = fminf(fmaxf(x * 2.885390081777927f, -28.f), 28.f);
    float tt = y + 12582912.f;
    int   ik = __float_as_int(tt) - 0x4B400000;
    float f  = y - (tt - 12582912.f);
    float p  = 1.5403530393e-4f;
    p = fmaf(p, f, 1.3333558146e-3f);
    p = fmaf(p, f, 9.6181291076e-3f);
    p = fmaf(p, f, 5.5504108664e-2f);
    p = fmaf(p, f, 2.4022650696e-1f);
    p = fmaf(p, f, 6.9314718056e-1f);
    p = fmaf(p, f, 1.0f);
    float e = __int_as_float(__float_as_int(p) + (ik << 23));
    float d = e + 1.0f;
    float r = __int_as_float(0x7EF311C3 - __float_as_int(d));
    r = r * (2.0f - d * r);
    r = r * (2.0f - d * r);
    return (e - 1.0f) * r;
}

// ---------------- 2-stage cp.async tf32 GEMM (pool-based smem) ----------------
// C[64, n0:n0+128] = A[64, ...] @ B[..., K]^T  over k0..k0+32*niter
__device__ __forceinline__ void gemm_issue(
    unsigned a_base, unsigned b_base,
    const float* __restrict__ A, int lda,
    const float* __restrict__ Bm, int ldb,
    int n0, int kb, int tid)
{
#pragma unroll
    for (int i = 0; i < 2; i++) {
        int idx = tid + i * 256;
        int rr = idx >> 3, kq = idx & 7;
        cp_async16(a_base + (unsigned)((rr * 32 + ((kq ^ (rr & 7)) << 2)) * 4),
                   A + (size_t)rr * lda + kb + kq * 4);
    }
#pragma unroll
    for (int i = 0; i < 4; i++) {
        int idx = tid + i * 256;
        int rr = idx >> 3, kq = idx & 7;
        cp_async16(b_base + (unsigned)((rr * 32 + ((kq ^ (rr & 7)) << 2)) * 4),
                   Bm + (size_t)(n0 + rr) * ldb + kb + kq * 4);
    }
    cp_commit();
}

// pool layout: As[2][64*32] at pool, Bs[2][128*32] at pool + 4096
__device__ __forceinline__ void gemm_async_pool(
    float* pool,
    const float* __restrict__ A, int lda,
    const float* __restrict__ Bm, int ldb,
    float* __restrict__ C, int ldc,
    int n0, int k0, int niter)
{
    float* As = pool;
    float* Bs = pool + 2 * 64 * 32;

    const int tid  = threadIdx.x;
    const int lane = tid & 31;
    const int warp = tid >> 5;
    const int wm = warp >> 2;
    const int wn = warp & 3;
    const int fr = lane >> 2;
    const int fc = lane & 3;

    unsigned sA = (unsigned)__cvta_generic_to_shared(As);
    unsigned sB = (unsigned)__cvta_generic_to_shared(Bs);

    float acc[2][4][4];
#pragma unroll
    for (int mi = 0; mi < 2; mi++)
#pragma unroll
        for (int ni = 0; ni < 4; ni++)
#pragma unroll
            for (int j = 0; j < 4; j++) acc[mi][ni][j] = 0.f;

    gemm_issue(sA, sB, A, lda, Bm, ldb, n0, k0, tid);

    for (int it = 0; it < niter; it++) {
        if (it + 1 < niter) {
            int st = (it + 1) & 1;
            gemm_issue(sA + st * 64 * 32 * 4, sB + st * 128 * 32 * 4,
                       A, lda, Bm, ldb, n0, k0 + (it + 1) * 32, tid);
            cp_wait1();
        } else {
            cp_wait0();
        }
        __syncthreads();

        const unsigned* as = (const unsigned*)(As + (it & 1) * 64 * 32);
        const unsigned* bs = (const unsigned*)(Bs + (it & 1) * 128 * 32);
#pragma unroll
        for (int ks = 0; ks < 4; ks++) {
            unsigned afr[2][4], bfr[4][2];
#pragma unroll
            for (int mi = 0; mi < 2; mi++) {
                int r0 = wm * 32 + mi * 16 + fr;
                int r1 = r0 + 8;
                int g0 = ((ks * 2)     ^ (r0 & 7)) << 2;
                int g1 = ((ks * 2 + 1) ^ (r0 & 7)) << 2;
                afr[mi][0] = as[r0 * 32 + g0 + fc];
                afr[mi][1] = as[r1 * 32 + g0 + fc];
                afr[mi][2] = as[r0 * 32 + g1 + fc];
                afr[mi][3] = as[r1 * 32 + g1 + fc];
            }
#pragma unroll
            for (int ni = 0; ni < 4; ni++) {
                int nr = wn * 32 + ni * 8 + fr;
                int g0 = ((ks * 2)     ^ (nr & 7)) << 2;
                int g1 = ((ks * 2 + 1) ^ (nr & 7)) << 2;
                bfr[ni][0] = bs[nr * 32 + g0 + fc];
                bfr[ni][1] = bs[nr * 32 + g1 + fc];
            }
#pragma unroll
            for (int mi = 0; mi < 2; mi++)
#pragma unroll
                for (int ni = 0; ni < 4; ni++)
                    mma_tf32(acc[mi][ni], afr[mi], bfr[ni]);
        }
        __syncthreads();
    }

#pragma unroll
    for (int mi = 0; mi < 2; mi++) {
        int row = wm * 32 + mi * 16 + fr;
#pragma unroll
        for (int ni = 0; ni < 4; ni++) {
            int col = n0 + wn * 32 + ni * 8 + fc * 2;
            *(float2*)&C[(size_t)row * ldc + col] =
                make_float2(acc[mi][ni][0], acc[mi][ni][1]);
            *(float2*)&C[(size_t)(row + 8) * ldc + col] =
                make_float2(acc[mi][ni][2], acc[mi][ni][3]);
        }
    }
}

// ---------------- precompute GEMM kernel --------------------------------------
__global__ __launch_bounds__(256) void gemm_pre2(
    const float* __restrict__ A, int lda,
    const float* __restrict__ Bm, int ldb,
    float* __restrict__ C, int ldc, int niter) {
    __shared__ float pool[12288];
    gemm_async_pool(pool,
                    A + (size_t)blockIdx.y * 64 * lda, lda, Bm, ldb,
                    C + (size_t)blockIdx.y * 64 * ldc, ldc,
                    blockIdx.x * 128, 0, niter);
}

// ---------------- prep ---------------------------------------------------------
__global__ void k_prep(const float* __restrict__ h0,
                       const float* __restrict__ Wq,
                       const float* __restrict__ W_hh,
                       const float* __restrict__ W_ih,
                       const float* __restrict__ Wc,
                       const float* __restrict__ ctx) {
    int stride = gridDim.x * blockDim.x;
    int tid0 = blockIdx.x * blockDim.x + threadIdx.x;
    if (tid0 == 0) { g_cnt = 0; g_gen = 0; }
    for (int i = tid0; i < BH; i += stride) {
        float h = h0[i];
        g_h[i] = h;
        g_hr[i] = round_tf32(h);
    }
    for (int i = tid0; i < H * H; i += stride)
        g_Wq[i] = round_tf32(Wq[i]);
    for (int i = tid0; i < G3 * H; i += stride)
        g_Whh[i] = round_tf32(W_hh[i]);
    for (size_t i = tid0; i < (size_t)G3 * CDIM; i += stride) {
        size_t r = i / CDIM, c = i - r * CDIM;
        g_Wihc[i] = round_tf32(W_ih[r * XK + E + c]);
    }
    for (size_t i = tid0; i < (size_t)G3 * E; i += stride) {
        size_t r = i / E, c = i - r * E;
        g_Wihe[i] = round_tf32(W_ih[r * XK + c]);
    }
    for (size_t i = tid0; i < (size_t)H * CDIM; i += stride)
        g_Wcr[i] = round_tf32(Wc[i]);
    for (size_t i = tid0; i < (size_t)B * L * CDIM; i += stride)
        g_ctxr[i] = round_tf32(ctx[i]);
}

// ---------------- embedding gather ---------------------------------------------
__global__ void k_emb(const int* __restrict__ tgt,
                      const float* __restrict__ emb,
                      float* __restrict__ out) {
    int row = blockIdx.x;
    int tok = tgt[row];
    float4 s = ((const float4*)(emb + (size_t)tok * E))[threadIdx.x];
    ((float4*)(out + (size_t)row * OC + H))[threadIdx.x] = s;
    float4 r = {round_tf32(s.x), round_tf32(s.y), round_tf32(s.z), round_tf32(s.w)};
    ((float4*)(g_xemb + (size_t)row * E))[threadIdx.x] = r;
}

// ---------------- persistent 64-step loop ---------------------------------------
__global__ __launch_bounds__(NTHR, 2)
void k_persist(const float* __restrict__ ctx,
               const float* __restrict__ bq,
               const float* __restrict__ v,
               const float* __restrict__ b_ih,
               const float* __restrict__ b_hh,
               float* __restrict__ out)
{
    const int bid = blockIdx.x;
    const int tid = threadIdx.x;

    __shared__ float s_pool[12288];   // 48 KB, aliased by all phases
    float* s_q    = s_pool;                      // 1024 floats
    float* s_v    = s_pool + 1024;               // 1024 floats
    float* s_attn = s_pool + 2048;               // 64 floats
    float4* s_part = (float4*)(s_pool + 2112);   // 128 float4

    for (int t = 0; t < S; t++) {
        // ===== P1: q split-K8 (tasks 0-63) + gh split-K8 (tasks 64-255) =====
        if (bid < 64) {
            int nt = bid & 7, ks = bid >> 3;             // kc=128
            gemm_async_pool(s_pool, g_hr, H, g_Wq, H,
                            g_qpart + ks * BH, H, nt * 128, ks * 128, 4);
        } else if (bid < 256) {
            int u = bid - 64;
            int nt = u % 24, ks = u / 24;                 // ks 0..7, kc=128
            gemm_async_pool(s_pool, g_hr, H, g_Whh, H,
                            g_ghpart + (size_t)ks * BG3, G3, nt * 128, ks * 128, 4);
        }
        gsync();

        // ===== P2: scores (tasks 0-255: 4 blocks/batch, 16 rows each) =====
        if (bid < 256) {
            const int b = bid >> 2, rg = bid & 3;
            float4 q = ((const float4*)bq)[tid];
#pragma unroll
            for (int p = 0; p < 8; p++) {
                float4 qp = ((const float4*)(g_qpart + p * BH + b * H))[tid];
                q.x += qp.x; q.y += qp.y; q.z += qp.z; q.w += qp.w;
            }
            ((float4*)s_q)[tid] = q;
            ((float4*)s_v)[tid] = ((const float4*)v)[tid];
            __syncthreads();

            const int w = tid >> 5, lane = tid & 31;
#pragma unroll
            for (int rep = 0; rep < 2; rep++) {
                const int l = rg * 16 + rep * 8 + w;
                const float4* cp = (const float4*)(g_ctxproj + ((size_t)(b * L + l)) * H);
                float acc = 0.f;
#pragma unroll
                for (int i = 0; i < 8; i++) {
                    int c4 = i * 32 + lane;
                    float4 c = cp[c4];
                    float4 qq = ((const float4*)s_q)[c4];
                    float4 vv = ((const float4*)s_v)[c4];
                    acc += vv.x * tanh_fast(c.x + qq.x) + vv.y * tanh_fast(c.y + qq.y)
                         + vv.z * tanh_fast(c.z + qq.z) + vv.w * tanh_fast(c.w + qq.w);
                }
#pragma unroll
                for (int o = 16; o; o >>= 1) acc += __shfl_xor_sync(0xffffffffu, acc, o);
                if (lane == 0) g_score[b * L + l] = acc;
            }
        }
        gsync();

        // ===== P3: 512 tasks over 296 blocks (2 passes) =====
#pragma unroll 1
        for (int pass = 0; pass < 2; pass++) {
            int task = bid + pass * NBLK;
            if (task < 256) {
                // ---- group A: softmax + ctx_t quarter -> out
                const int b = task >> 2, qd = task & 3;
                if (tid < 32) {
                    float s0 = g_score[b * L + tid];
                    float s1 = g_score[b * L + 32 + tid];
                    float m = fmaxf(s0, s1);
#pragma unroll
                    for (int o = 16; o; o >>= 1) m = fmaxf(m, __shfl_xor_sync(0xffffffffu, m, o));
                    float e0 = __expf(s0 - m), e1 = __expf(s1 - m);
                    float ss = e0 + e1;
#pragma unroll
                    for (int o = 16; o; o >>= 1) ss += __shfl_xor_sync(0xffffffffu, ss, o);
                    s_attn[tid] = e0 / ss; s_attn[tid + 32] = e1 / ss;
                }
                __syncthreads();

                const int c4l = tid & 127, piece = tid >> 7;
                const int c4 = qd * 128 + c4l;
                const float4* cb4 = (const float4*)(ctx + (size_t)b * L * CDIM);
                float4 acc = {0.f, 0.f, 0.f, 0.f};
                const int l0 = piece * 32;
#pragma unroll 8
                for (int l = l0; l < l0 + 32; l++) {
                    float a = s_attn[l];
                    float4 x = cb4[(size_t)l * (CDIM / 4) + c4];
                    acc.x = fmaf(a, x.x, acc.x); acc.y = fmaf(a, x.y, acc.y);
                    acc.z = fmaf(a, x.z, acc.z); acc.w = fmaf(a, x.w, acc.w);
                }
                if (piece == 1) s_part[c4l] = acc;
                __syncthreads();
                if (piece == 0) {
                    float4 o2 = s_part[c4l];
                    acc.x += o2.x; acc.y += o2.y; acc.z += o2.z; acc.w += o2.w;
                    ((float4*)(out + ((size_t)(b * S + t)) * OC + H + E))[c4] = acc;
                }
            } else if (task < 512) {
                // ---- group B: softmax + gi(ctxW) + gh-reduce + GRU update
                const int u = task - 256;
                const int b = u >> 2;
                const int i = (u & 3) * 256 + tid;
                if (tid < 32) {
                    float s0 = g_score[b * L + tid];
                    float s1 = g_score[b * L + 32 + tid];
                    float m = fmaxf(s0, s1);
#pragma unroll
                    for (int o = 16; o; o >>= 1) m = fmaxf(m, __shfl_xor_sync(0xffffffffu, m, o));
                    float e0 = __expf(s0 - m), e1 = __expf(s1 - m);
                    float ss = e0 + e1;
#pragma unroll
                    for (int o = 16; o; o >>= 1) ss += __shfl_xor_sync(0xffffffffu, ss, o);
                    s_attn[tid] = e0 / ss; s_attn[tid + 32] = e1 / ss;
                }
                __syncthreads();

                const float* cw = g_ctxW + (size_t)b * L * G3;
                float gr = 0.f, gz = 0.f, gn = 0.f;
#pragma unroll 4
                for (int l = 0; l < L; l++) {
                    float a = s_attn[l];
                    const float* row = cw + (size_t)l * G3;
                    gr = fmaf(a, __ldg(row + i), gr);
                    gz = fmaf(a, __ldg(row + H + i), gz);
                    gn = fmaf(a, __ldg(row + 2 * H + i), gn);
                }

                const size_t ge = ((size_t)(b * S + t)) * G3;
                float ir  = b_ih[i]         + g_giemb[ge + i]         + gr;
                float iz  = b_ih[H + i]     + g_giemb[ge + H + i]     + gz;
                float in_ = b_ih[2 * H + i] + g_giemb[ge + 2 * H + i] + gn;
                float hr = b_hh[i], hz = b_hh[H + i], hn = b_hh[2 * H + i];
#pragma unroll
                for (int p = 0; p < 8; p++) {
                    const float* gp = g_ghpart + (size_t)p * BG3 + (size_t)b * G3;
                    hr += gp[i]; hz += gp[H + i]; hn += gp[2 * H + i];
                }
                float r = 1.f / (1.f + __expf(-(ir + hr)));
                float z = 1.f / (1.f + __expf(-(iz + hz)));
                float n = tanh_fast(in_ + r * hn);
                const int idx = b * H + i;
                float hold = g_h[idx];
                float hnew = (1.f - z) * n + z * hold;

                g_h[idx]  = hnew;
                g_hr[idx] = round_tf32(hnew);
                out[((size_t)(b * S + t)) * OC + i] = hold;
                if (t == S - 1)
                    out[(size_t)B * S * OC + idx] = hnew;
            }
            __syncthreads();
        }
        gsync();
    }
}

// -----------------------------------------------------------------------------
extern "C" void kernel_launch(void* const* d_in, const int* in_sizes, int n_in,
                              void* d_out, int out_size) {
    const int*   tgt  = (const int*)d_in[0];
    const float* ctx  = (const float*)d_in[1];
    const float* h0   = (const float*)d_in[2];
    const float* emb  = (const float*)d_in[3];
    const float* Wc   = (const float*)d_in[4];
    const float* Wq   = (const float*)d_in[5];
    const float* bq   = (const float*)d_in[6];
    const float* v    = (const float*)d_in[7];
    const float* W_ih = (const float*)d_in[8];
    const float* W_hh = (const float*)d_in[9];
    const float* b_ih = (const float*)d_in[10];
    const float* b_hh = (const float*)d_in[11];
    float* out = (float*)d_out;

    float *p_cp, *p_ge, *p_cr, *p_wcr, *p_xe, *p_wihe, *p_wihc, *p_cW;
    cudaGetSymbolAddress((void**)&p_cp,   g_ctxproj);
    cudaGetSymbolAddress((void**)&p_ge,   g_giemb);
    cudaGetSymbolAddress((void**)&p_cr,   g_ctxr);
    cudaGetSymbolAddress((void**)&p_wcr,  g_Wcr);
    cudaGetSymbolAddress((void**)&p_xe,   g_xemb);
    cudaGetSymbolAddress((void**)&p_wihe, g_Wihe);
    cudaGetSymbolAddress((void**)&p_wihc, g_Wihc);
    cudaGetSymbolAddress((void**)&p_cW,   g_ctxW);

    k_prep<<<1024, 256>>>(h0, Wq, W_hh, W_ih, Wc, ctx);
    k_emb<<<B * S, 128>>>(tgt, emb, out);

    // ctx_proj[B*L, H] = ctxR @ WcR^T
    gemm_pre2<<<dim3(H / 128, (B * L) / 64), 256>>>(p_cr, CDIM, p_wcr, CDIM, p_cp, H, 64);
    // gi_emb[B*S, 3H] = embR @ WiheR^T
    gemm_pre2<<<dim3(G3 / 128, (B * S) / 64), 256>>>(p_xe, E, p_wihe, E, p_ge, G3, 16);
    // ctxW[B*L, 3H] = ctxR @ WihcR^T   (gi = attn @ ctxW per step)
    gemm_pre2<<<dim3(G3 / 128, (B * L) / 64), 256>>>(p_cr, CDIM, p_wihc, CDIM, p_cW, G3, 64);

    // whole 64-step loop in one persistent kernel (3 grid barriers per step)
    k_persist<<<NBLK, NTHR>>>(ctx, bq, v, b_ih, b_hh, out);
}

// round 11
// speedup vs baseline: 1.2722x; 1.2722x over previous
#include <cuda_runtime.h>
#include <cuda_bf16.h>
#include <math.h>

#define B 64
#define S 64
#define L 64
#define H 1024
#define CDIM 2048
#define E 512
#define OC (H + E + CDIM)   // 3584
#define XK (E + CDIM)       // 2560
#define G3 (3 * H)          // 3072
#define BH (B * H)
#define BG3 (B * G3)

// ---------------- scratch (device globals) ----------------------------------
__device__ float g_ctxproj[B * L * H];            // 16.8 MB (fp32, precompute)
__device__ __nv_bfloat16 g_cpbf[B * L * H];       // 8.4 MB  (bf16 copy for scores)
__device__ float g_giemb[(size_t)B * S * G3];     // 50.3 MB
__device__ float g_h[BH];
__device__ float g_hr[BH];
__device__ float g_ctxt[B * CDIM];
__device__ float g_qpart[8 * BH];
__device__ float g_gipart[8 * (size_t)BG3];
__device__ float g_ghpart[4 * (size_t)BG3];
// pre-rounded weights / operands
__device__ float g_Wq[H * H];
__device__ float g_Whh[G3 * H];
__device__ float g_Wihc[(size_t)G3 * CDIM];
__device__ float g_Wihe[G3 * E];
__device__ float g_Wcr[H * CDIM];
__device__ float g_ctxr[B * L * CDIM];
__device__ float g_xemb[B * S * E];

// ---------------- PDL helpers --------------------------------------------------
__device__ __forceinline__ void pdl_wait() {
    asm volatile("griddepcontrol.wait;" ::: "memory");
}
__device__ __forceinline__ void pdl_launch_dep() {
    asm volatile("griddepcontrol.launch_dependents;" ::: "memory");
}

// ---------------- helpers ----------------------------------------------------
__device__ __forceinline__ unsigned f2tf32(float x) {
    unsigned y;
    asm("cvt.rna.tf32.f32 %0, %1;" : "=r"(y) : "f"(x));
    return y;
}
__device__ __forceinline__ float round_tf32(float x) {
    return __uint_as_float(f2tf32(x));
}
__device__ __forceinline__ float tanh_mufu(float x) {
    float y;
    asm("tanh.approx.f32 %0, %1;" : "=f"(y) : "f"(x));
    return y;
}
__device__ __forceinline__ void mma_tf32(float* c, const unsigned* a, const unsigned* b) {
    asm volatile(
        "mma.sync.aligned.m16n8k8.row.col.f32.tf32.tf32.f32 "
        "{%0,%1,%2,%3},{%4,%5,%6,%7},{%8,%9},{%0,%1,%2,%3};"
        : "+f"(c[0]), "+f"(c[1]), "+f"(c[2]), "+f"(c[3])
        : "r"(a[0]), "r"(a[1]), "r"(a[2]), "r"(a[3]), "r"(b[0]), "r"(b[1]));
}
__device__ __forceinline__ void cp_async16(unsigned dst, const void* src) {
    asm volatile("cp.async.cg.shared.global [%0], [%1], 16;" :: "r"(dst), "l"(src));
}
__device__ __forceinline__ void cp_commit() {
    asm volatile("cp.async.commit_group;");
}
__device__ __forceinline__ void cp_wait1() {
    asm volatile("cp.async.wait_group 1;");
}
__device__ __forceinline__ void cp_wait0() {
    asm volatile("cp.async.wait_group 0;");
}

// ---------------- FFMA-only precise tanh (gate path only) ---------------------
__device__ __forceinline__ float tanh_fast(float x) {
    float y = fminf(fmaxf(x * 2.885390081777927f, -28.f), 28.f);
    float tt = y + 12582912.f;
    int   ik = __float_as_int(tt) - 0x4B400000;
    float f  = y - (tt - 12582912.f);
    float p  = 1.5403530393e-4f;
    p = fmaf(p, f, 1.3333558146e-3f);
    p = fmaf(p, f, 9.6181291076e-3f);
    p = fmaf(p, f, 5.5504108664e-2f);
    p = fmaf(p, f, 2.4022650696e-1f);
    p = fmaf(p, f, 6.9314718056e-1f);
    p = fmaf(p, f, 1.0f);
    float e = __int_as_float(__float_as_int(p) + (ik << 23));
    float d = e + 1.0f;
    float r = __int_as_float(0x7EF311C3 - __float_as_int(d));
    r = r * (2.0f - d * r);
    r = r * (2.0f - d * r);
    return (e - 1.0f) * r;
}

// ---------------- 256-thread 2-stage cp.async tf32 GEMM ----------------------
__device__ __forceinline__ void gemm_issue(
    unsigned a_base, unsigned b_base,
    const float* __restrict__ A, int lda,
    const float* __restrict__ Bm, int ldb,
    int n0, int kb, int tid)
{
#pragma unroll
    for (int i = 0; i < 2; i++) {
        int idx = tid + i * 256;
        int rr = idx >> 3, kq = idx & 7;
        cp_async16(a_base + (unsigned)((rr * 32 + ((kq ^ (rr & 7)) << 2)) * 4),
                   A + (size_t)rr * lda + kb + kq * 4);
    }
#pragma unroll
    for (int i = 0; i < 4; i++) {
        int idx = tid + i * 256;
        int rr = idx >> 3, kq = idx & 7;
        cp_async16(b_base + (unsigned)((rr * 32 + ((kq ^ (rr & 7)) << 2)) * 4),
                   Bm + (size_t)(n0 + rr) * ldb + kb + kq * 4);
    }
    cp_commit();
}

__device__ __forceinline__ void gemm_async_rt(
    const float* __restrict__ A, int lda,
    const float* __restrict__ Bm, int ldb,
    float* __restrict__ C, int ldc,
    int n0, int k0, int niter)
{
    __shared__ float As[2][64 * 32];
    __shared__ float Bs[2][128 * 32];

    const int tid  = threadIdx.x;
    const int lane = tid & 31;
    const int warp = tid >> 5;
    const int wm = warp >> 2;
    const int wn = warp & 3;
    const int fr = lane >> 2;
    const int fc = lane & 3;

    unsigned sA = (unsigned)__cvta_generic_to_shared(&As[0][0]);
    unsigned sB = (unsigned)__cvta_generic_to_shared(&Bs[0][0]);

    float acc[2][4][4];
#pragma unroll
    for (int mi = 0; mi < 2; mi++)
#pragma unroll
        for (int ni = 0; ni < 4; ni++)
#pragma unroll
            for (int j = 0; j < 4; j++) acc[mi][ni][j] = 0.f;

    gemm_issue(sA, sB, A, lda, Bm, ldb, n0, k0, tid);

    for (int it = 0; it < niter; it++) {
        if (it + 1 < niter) {
            int st = (it + 1) & 1;
            gemm_issue(sA + st * 64 * 32 * 4, sB + st * 128 * 32 * 4,
                       A, lda, Bm, ldb, n0, k0 + (it + 1) * 32, tid);
            cp_wait1();
        } else {
            cp_wait0();
        }
        __syncthreads();

        const unsigned* as = (const unsigned*)As[it & 1];
        const unsigned* bs = (const unsigned*)Bs[it & 1];
#pragma unroll
        for (int ks = 0; ks < 4; ks++) {
            unsigned afr[2][4], bfr[4][2];
#pragma unroll
            for (int mi = 0; mi < 2; mi++) {
                int r0 = wm * 32 + mi * 16 + fr;
                int r1 = r0 + 8;
                int g0 = ((ks * 2)     ^ (r0 & 7)) << 2;
                int g1 = ((ks * 2 + 1) ^ (r0 & 7)) << 2;
                afr[mi][0] = as[r0 * 32 + g0 + fc];
                afr[mi][1] = as[r1 * 32 + g0 + fc];
                afr[mi][2] = as[r0 * 32 + g1 + fc];
                afr[mi][3] = as[r1 * 32 + g1 + fc];
            }
#pragma unroll
            for (int ni = 0; ni < 4; ni++) {
                int nr = wn * 32 + ni * 8 + fr;
                int g0 = ((ks * 2)     ^ (nr & 7)) << 2;
                int g1 = ((ks * 2 + 1) ^ (nr & 7)) << 2;
                bfr[ni][0] = bs[nr * 32 + g0 + fc];
                bfr[ni][1] = bs[nr * 32 + g1 + fc];
            }
#pragma unroll
            for (int mi = 0; mi < 2; mi++)
#pragma unroll
                for (int ni = 0; ni < 4; ni++)
                    mma_tf32(acc[mi][ni], afr[mi], bfr[ni]);
        }
        __syncthreads();
    }

#pragma unroll
    for (int mi = 0; mi < 2; mi++) {
        int row = wm * 32 + mi * 16 + fr;
#pragma unroll
        for (int ni = 0; ni < 4; ni++) {
            int col = n0 + wn * 32 + ni * 8 + fc * 2;
            *(float2*)&C[(size_t)row * ldc + col] =
                make_float2(acc[mi][ni][0], acc[mi][ni][1]);
            *(float2*)&C[(size_t)(row + 8) * ldc + col] =
                make_float2(acc[mi][ni][2], acc[mi][ni][3]);
        }
    }
}

// ---------------- 1024-thread GEMM tile (pool smem; gh inside k2) -------------
__device__ __forceinline__ void gemm_issue1024(
    unsigned a_base, unsigned b_base,
    const float* __restrict__ A, int lda,
    const float* __restrict__ Bm, int ldb,
    int n0, int kb, int tid)
{
    if (tid < 512) {
        int rr = tid >> 3, kq = tid & 7;
        cp_async16(a_base + (unsigned)((rr * 32 + ((kq ^ (rr & 7)) << 2)) * 4),
                   A + (size_t)rr * lda + kb + kq * 4);
    }
    int rr = tid >> 3, kq = tid & 7;
    cp_async16(b_base + (unsigned)((rr * 32 + ((kq ^ (rr & 7)) << 2)) * 4),
               Bm + (size_t)(n0 + rr) * ldb + kb + kq * 4);
    cp_commit();
}

template <int NITER>
__device__ __forceinline__ void gemm_async1024_pool(
    float* pool,
    const float* __restrict__ A, int lda,
    const float* __restrict__ Bm, int ldb,
    float* __restrict__ C, int ldc,
    int n0, int k0)
{
    float* As2 = pool;                 // [2][64*32]
    float* Bs2 = pool + 2 * 64 * 32;   // [2][128*32]

    const int tid  = threadIdx.x;
    const int lane = tid & 31;
    const int warp = tid >> 5;       // 0..31
    const int wm = warp >> 4;        // 0..1
    const int wn = warp & 15;        // 0..15
    const int fr = lane >> 2;
    const int fc = lane & 3;

    unsigned sA = (unsigned)__cvta_generic_to_shared(As2);
    unsigned sB = (unsigned)__cvta_generic_to_shared(Bs2);

    float acc[2][4];
#pragma unroll
    for (int mi = 0; mi < 2; mi++)
#pragma unroll
        for (int j = 0; j < 4; j++) acc[mi][j] = 0.f;

    gemm_issue1024(sA, sB, A, lda, Bm, ldb, n0, k0, tid);

#pragma unroll
    for (int it = 0; it < NITER; it++) {
        if (it + 1 < NITER) {
            int st = (it + 1) & 1;
            gemm_issue1024(sA + st * 64 * 32 * 4, sB + st * 128 * 32 * 4,
                           A, lda, Bm, ldb, n0, k0 + (it + 1) * 32, tid);
            cp_wait1();
        } else {
            cp_wait0();
        }
        __syncthreads();

        const unsigned* as = (const unsigned*)(As2 + (it & 1) * 64 * 32);
        const unsigned* bs = (const unsigned*)(Bs2 + (it & 1) * 128 * 32);
#pragma unroll
        for (int ks = 0; ks < 4; ks++) {
            unsigned afr[2][4], bfr[2];
#pragma unroll
            for (int mi = 0; mi < 2; mi++) {
                int r0 = wm * 32 + mi * 16 + fr;
                int r1 = r0 + 8;
                int g0 = ((ks * 2)     ^ (r0 & 7)) << 2;
                int g1 = ((ks * 2 + 1) ^ (r0 & 7)) << 2;
                afr[mi][0] = as[r0 * 32 + g0 + fc];
                afr[mi][1] = as[r1 * 32 + g0 + fc];
                afr[mi][2] = as[r0 * 32 + g1 + fc];
                afr[mi][3] = as[r1 * 32 + g1 + fc];
            }
            {
                int nr = wn * 8 + fr;
                int g0 = ((ks * 2)     ^ (nr & 7)) << 2;
                int g1 = ((ks * 2 + 1) ^ (nr & 7)) << 2;
                bfr[0] = bs[nr * 32 + g0 + fc];
                bfr[1] = bs[nr * 32 + g1 + fc];
            }
#pragma unroll
            for (int mi = 0; mi < 2; mi++)
                mma_tf32(acc[mi], afr[mi], bfr);
        }
        __syncthreads();
    }

#pragma unroll
    for (int mi = 0; mi < 2; mi++) {
        int row = wm * 32 + mi * 16 + fr;
        int col = n0 + wn * 8 + fc * 2;
        *(float2*)&C[(size_t)row * ldc + col] = make_float2(acc[mi][0], acc[mi][1]);
        *(float2*)&C[(size_t)(row + 8) * ldc + col] = make_float2(acc[mi][2], acc[mi][3]);
    }
}

// ---------------- precompute GEMM kernel --------------------------------------
__global__ __launch_bounds__(256) void gemm_pre2(
    const float* __restrict__ A, int lda,
    const float* __restrict__ Bm, int ldb,
    float* __restrict__ C, int ldc, int niter) {
    gemm_async_rt(A + (size_t)blockIdx.y * 64 * lda, lda, Bm, ldb,
                  C + (size_t)blockIdx.y * 64 * ldc, ldc,
                  blockIdx.x * 128, 0, niter);
}

// ---------------- ctxproj -> bf16 conversion -----------------------------------
__global__ void k_cvt_bf() {
    int stride = gridDim.x * blockDim.x;
    for (int i = blockIdx.x * blockDim.x + threadIdx.x;
         i < B * L * H / 2; i += stride) {
        float2 x = ((const float2*)g_ctxproj)[i];
        ((__nv_bfloat162*)g_cpbf)[i] = __float22bfloat162_rn(x);
    }
}

// ---------------- prep ---------------------------------------------------------
__global__ void k_prep(const float* __restrict__ h0,
                       const float* __restrict__ Wq,
                       const float* __restrict__ W_hh,
                       const float* __restrict__ W_ih,
                       const float* __restrict__ Wc,
                       const float* __restrict__ ctx) {
    int stride = gridDim.x * blockDim.x;
    int tid0 = blockIdx.x * blockDim.x + threadIdx.x;
    for (int i = tid0; i < BH; i += stride) {
        float h = h0[i];
        g_h[i] = h;
        g_hr[i] = round_tf32(h);
    }
    for (int i = tid0; i < H * H; i += stride)
        g_Wq[i] = round_tf32(Wq[i]);
    for (int i = tid0; i < G3 * H; i += stride)
        g_Whh[i] = round_tf32(W_hh[i]);
    for (size_t i = tid0; i < (size_t)G3 * CDIM; i += stride) {
        size_t r = i / CDIM, c = i - r * CDIM;
        g_Wihc[i] = round_tf32(W_ih[r * XK + E + c]);
    }
    for (size_t i = tid0; i < (size_t)G3 * E; i += stride) {
        size_t r = i / E, c = i - r * E;
        g_Wihe[i] = round_tf32(W_ih[r * XK + c]);
    }
    for (size_t i = tid0; i < (size_t)H * CDIM; i += stride)
        g_Wcr[i] = round_tf32(Wc[i]);
    for (size_t i = tid0; i < (size_t)B * L * CDIM; i += stride)
        g_ctxr[i] = round_tf32(ctx[i]);
}

// ---------------- embedding gather ---------------------------------------------
__global__ void k_emb(const int* __restrict__ tgt,
                      const float* __restrict__ emb,
                      float* __restrict__ out) {
    int row = blockIdx.x;
    int tok = tgt[row];
    float4 s = ((const float4*)(emb + (size_t)tok * E))[threadIdx.x];
    ((float4*)(out + (size_t)row * OC + H))[threadIdx.x] = s;
    float4 r = {round_tf32(s.x), round_tf32(s.y), round_tf32(s.z), round_tf32(s.w)};
    ((float4*)(g_xemb + (size_t)row * E))[threadIdx.x] = r;
}

// ---------------- K1: q partials (64 blk) ---------------------------------------
__global__ __launch_bounds__(256) void k1_q() {
    pdl_wait();
    int nt = blockIdx.x & 7, ks = blockIdx.x >> 3;   // kc = 128
    gemm_async_rt(g_hr, H, g_Wq, H, g_qpart + ks * BH, H, nt * 128, ks * 128, 4);
    pdl_launch_dep();
}

// ---------------- K2: attention (blk 0-127, 2/batch) + gh GEMM (blk 128-223) ----
__global__ __launch_bounds__(1024) void k2_attn(
    const float* __restrict__ ctx,
    const float* __restrict__ bq,
    const float* __restrict__ v,
    float* __restrict__ out, int t)
{
    const int tid = threadIdx.x;
    __shared__ float pool[12288];    // 48 KB, aliased by both paths

    if (blockIdx.x >= 128) {
        // gh partials (depends only on h, via k1's PDL chain)
        pdl_wait();
        int u = blockIdx.x - 128;
        int nt = u % 24, ks = u / 24;                 // ks 0..3, kc=256
        gemm_async1024_pool<8>(pool, g_hr, H, g_Whh, H,
                               g_ghpart + (size_t)ks * BG3, G3, nt * 128, ks * 256);
        pdl_launch_dep();
        return;
    }

    const int b = blockIdx.x >> 1;
    const int half = blockIdx.x & 1;
    float*  s_q    = pool;                       // 1024
    float*  s_v    = pool + 1024;                // 1024
    float*  s_attn = pool + 2048;                // 64
    float4* s_part = (float4*)(pool + 2112);     // up to 768 float4

    pdl_wait();

    // q-partial reduction: 512 threads (2 groups of 4 partials), +bq in group 0
    if (tid < 512) {
        int c4 = tid & 255, grp = tid >> 8;
        float4 q = (grp == 0) ? ((const float4*)bq)[c4]
                              : make_float4(0.f, 0.f, 0.f, 0.f);
#pragma unroll
        for (int p = 0; p < 4; p++) {
            float4 qp = ((const float4*)(g_qpart + (grp * 4 + p) * BH + b * H))[c4];
            q.x += qp.x; q.y += qp.y; q.z += qp.z; q.w += qp.w;
        }
        s_part[tid] = q;
    } else if (tid < 768) {
        ((float4*)s_v)[tid - 512] = ((const float4*)v)[tid - 512];
    }
    __syncthreads();
    if (tid < 256) {
        float4 a = s_part[tid], c = s_part[tid + 256];
        ((float4*)s_q)[tid] = make_float4(a.x + c.x, a.y + c.y, a.z + c.z, a.w + c.w);
    }
    __syncthreads();

    // scores via MUFU tanh on bf16 ctxproj: 32 warps, 2 rows each
    {
        const int w = tid >> 5, lane = tid & 31;
#pragma unroll
        for (int rep = 0; rep < 2; rep++) {
            int l = w + rep * 32;
            const __nv_bfloat162* cp =
                (const __nv_bfloat162*)(g_cpbf + ((size_t)(b * L + l)) * H);
            float acc = 0.f;
#pragma unroll
            for (int j = 0; j < 16; j++) {
                int c2 = j * 32 + lane;
                float2 c = __bfloat1622float2(cp[c2]);
                float2 q = ((const float2*)s_q)[c2];
                float2 vv = ((const float2*)s_v)[c2];
                acc += vv.x * tanh_mufu(c.x + q.x) + vv.y * tanh_mufu(c.y + q.y);
            }
#pragma unroll
            for (int o = 16; o; o >>= 1) acc += __shfl_xor_sync(0xffffffffu, acc, o);
            if (lane == 0) s_attn[l] = acc;
        }
    }
    __syncthreads();

    // softmax (warp 0)
    if (tid < 32) {
        float s0 = s_attn[tid], s1 = s_attn[tid + 32];
        float m = fmaxf(s0, s1);
#pragma unroll
        for (int o = 16; o; o >>= 1) m = fmaxf(m, __shfl_xor_sync(0xffffffffu, m, o));
        float e0 = __expf(s0 - m), e1 = __expf(s1 - m);
        float ss = e0 + e1;
#pragma unroll
        for (int o = 16; o; o >>= 1) ss += __shfl_xor_sync(0xffffffffu, ss, o);
        s_attn[tid] = e0 / ss; s_attn[tid + 32] = e1 / ss;
    }
    __syncthreads();

    // ctx_t for this block's half (1024 cols): 4 threads per float4-col, 16 rows each
    {
        const int c4l = tid & 255;                 // 0..255 within half
        const int piece = tid >> 8;                // 0..3
        const int c4 = half * 256 + c4l;           // global float4 col
        const float4* cb4 = (const float4*)(ctx + (size_t)b * L * CDIM);
        float4 acc = {0.f, 0.f, 0.f, 0.f};
        const int l0 = piece * 16;
#pragma unroll 8
        for (int l = l0; l < l0 + 16; l++) {
            float a = s_attn[l];
            float4 x = cb4[(size_t)l * (CDIM / 4) + c4];
            acc.x = fmaf(a, x.x, acc.x); acc.y = fmaf(a, x.y, acc.y);
            acc.z = fmaf(a, x.z, acc.z); acc.w = fmaf(a, x.w, acc.w);
        }
        if (piece > 0) s_part[(piece - 1) * 256 + c4l] = acc;
        __syncthreads();
        if (piece == 0) {
            float4 p1 = s_part[c4l];
            float4 p2 = s_part[256 + c4l];
            float4 p3 = s_part[512 + c4l];
            acc.x += p1.x + p2.x + p3.x;
            acc.y += p1.y + p2.y + p3.y;
            acc.z += p1.z + p2.z + p3.z;
            acc.w += p1.w + p2.w + p3.w;
            ((float4*)(out + ((size_t)(b * S + t)) * OC + H + E))[c4] = acc;
            float4 rr = {round_tf32(acc.x), round_tf32(acc.y),
                         round_tf32(acc.z), round_tf32(acc.w)};
            ((float4*)(g_ctxt + (size_t)b * CDIM))[c4] = rr;
        }
    }
    pdl_launch_dep();
}

// ---------------- K3: gi partials (192 blk) -------------------------------------
__global__ __launch_bounds__(256) void k3_gi() {
    pdl_wait();
    int nt = blockIdx.x % 24, ks = blockIdx.x / 24;   // ks 0..7, kc=256
    gemm_async_rt(g_ctxt, CDIM, g_Wihc, CDIM,
                  g_gipart + (size_t)ks * BG3, G3, nt * 128, ks * 256, 8);
    pdl_launch_dep();
}

// ---------------- K4: GRU update ------------------------------------------------
__global__ __launch_bounds__(256) void k4_update(
    const float* __restrict__ b_ih, const float* __restrict__ b_hh,
    float* __restrict__ out, int t)
{
    const int idx = blockIdx.x * 256 + threadIdx.x;
    const int b = idx >> 10, i = idx & (H - 1);
    const size_t ge = ((size_t)(b * S + t)) * G3;

    pdl_wait();

    float ir  = b_ih[i]         + g_giemb[ge + i];
    float iz  = b_ih[H + i]     + g_giemb[ge + H + i];
    float in_ = b_ih[2 * H + i] + g_giemb[ge + 2 * H + i];
#pragma unroll
    for (int p = 0; p < 8; p++) {
        const float* gp = g_gipart + (size_t)p * BG3 + (size_t)b * G3;
        ir += gp[i]; iz += gp[H + i]; in_ += gp[2 * H + i];
    }
    float hr = b_hh[i], hz = b_hh[H + i], hn = b_hh[2 * H + i];
#pragma unroll
    for (int p = 0; p < 4; p++) {
        const float* gp = g_ghpart + (size_t)p * BG3 + (size_t)b * G3;
        hr += gp[i]; hz += gp[H + i]; hn += gp[2 * H + i];
    }
    float r = 1.f / (1.f + __expf(-(ir + hr)));
    float z = 1.f / (1.f + __expf(-(iz + hz)));
    float n = tanh_fast(in_ + r * hn);
    float hold = g_h[idx];
    float hnew = (1.f - z) * n + z * hold;

    g_h[idx]  = hnew;
    g_hr[idx] = round_tf32(hnew);
    out[((size_t)(b * S + t)) * OC + i] = hold;
    if (t == S - 1)
        out[(size_t)B * S * OC + idx] = hnew;

    pdl_launch_dep();
}

// -----------------------------------------------------------------------------
template <typename... Args>
static inline void launch_pdl(void (*kern)(Args...), dim3 grid, dim3 blk,
                              Args... args) {
    cudaLaunchConfig_t cfg = {};
    cfg.gridDim = grid;
    cfg.blockDim = blk;
    cfg.dynamicSmemBytes = 0;
    cfg.stream = 0;
    cudaLaunchAttribute attr[1];
    attr[0].id = cudaLaunchAttributeProgrammaticStreamSerialization;
    attr[0].val.programmaticStreamSerializationAllowed = 1;
    cfg.attrs = attr;
    cfg.numAttrs = 1;
    cudaLaunchKernelEx(&cfg, kern, args...);
}

extern "C" void kernel_launch(void* const* d_in, const int* in_sizes, int n_in,
                              void* d_out, int out_size) {
    const int*   tgt  = (const int*)d_in[0];
    const float* ctx  = (const float*)d_in[1];
    const float* h0   = (const float*)d_in[2];
    const float* emb  = (const float*)d_in[3];
    const float* Wc   = (const float*)d_in[4];
    const float* Wq   = (const float*)d_in[5];
    const float* bq   = (const float*)d_in[6];
    const float* v    = (const float*)d_in[7];
    const float* W_ih = (const float*)d_in[8];
    const float* W_hh = (const float*)d_in[9];
    const float* b_ih = (const float*)d_in[10];
    const float* b_hh = (const float*)d_in[11];
    float* out = (float*)d_out;

    float *p_cp, *p_ge, *p_cr, *p_wcr, *p_xe, *p_wihe;
    cudaGetSymbolAddress((void**)&p_cp,   g_ctxproj);
    cudaGetSymbolAddress((void**)&p_ge,   g_giemb);
    cudaGetSymbolAddress((void**)&p_cr,   g_ctxr);
    cudaGetSymbolAddress((void**)&p_wcr,  g_Wcr);
    cudaGetSymbolAddress((void**)&p_xe,   g_xemb);
    cudaGetSymbolAddress((void**)&p_wihe, g_Wihe);

    k_prep<<<1024, 256>>>(h0, Wq, W_hh, W_ih, Wc, ctx);
    k_emb<<<B * S, 128>>>(tgt, emb, out);

    // ctx_proj[B*L, H] = ctxR @ WcR^T
    gemm_pre2<<<dim3(H / 128, (B * L) / 64), 256>>>(p_cr, CDIM, p_wcr, CDIM, p_cp, H, 64);
    // bf16 copy of ctx_proj for the scores path
    k_cvt_bf<<<1024, 256>>>();
    // gi_emb[B*S, 3H] = embR @ WiheR^T
    gemm_pre2<<<dim3(G3 / 128, (B * S) / 64), 256>>>(p_xe, E, p_wihe, E, p_ge, G3, 16);

    for (int t = 0; t < S; t++) {
        launch_pdl(k1_q, dim3(64), dim3(256));
        launch_pdl(k2_attn, dim3(224), dim3(1024), ctx, bq, v, out, t);
        launch_pdl(k3_gi, dim3(192), dim3(256));
        launch_pdl(k4_update, dim3(BH / 256), dim3(256), b_ih, b_hh, out, t);
    }
}

// round 12
// speedup vs baseline: 1.4773x; 1.1612x over previous
#include <cuda_runtime.h>
#include <cuda_bf16.h>
#include <math.h>

#define B 64
#define S 64
#define L 64
#define H 1024
#define CDIM 2048
#define E 512
#define OC (H + E + CDIM)   // 3584
#define XK (E + CDIM)       // 2560
#define G3 (3 * H)          // 3072
#define BH (B * H)
#define BG3 (B * G3)

// ---------------- scratch (device globals) ----------------------------------
__device__ float g_ctxproj[B * L * H];            // 16.8 MB (fp32, precompute)
__device__ __nv_bfloat16 g_cpbf[B * L * H];       // 8.4 MB  (bf16 copy for scores)
__device__ float g_giemb[(size_t)B * S * G3];     // 50.3 MB
__device__ float g_h[BH];
__device__ float g_hr[BH];
__device__ float g_ctxt[B * CDIM];
__device__ float g_qpart[8 * BH];
__device__ float g_gipart[8 * (size_t)BG3];
__device__ float g_ghpart[4 * (size_t)BG3];
// pre-rounded weights / operands
__device__ float g_Wq[H * H];
__device__ float g_Whh[G3 * H];
__device__ float g_Wihc[(size_t)G3 * CDIM];
__device__ float g_Wihe[G3 * E];
__device__ float g_Wcr[H * CDIM];
__device__ float g_ctxr[B * L * CDIM];
__device__ float g_xemb[B * S * E];

// ---------------- PDL helpers --------------------------------------------------
__device__ __forceinline__ void pdl_wait() {
    asm volatile("griddepcontrol.wait;" ::: "memory");
}
__device__ __forceinline__ void pdl_launch_dep() {
    asm volatile("griddepcontrol.launch_dependents;" ::: "memory");
}

// ---------------- helpers ----------------------------------------------------
__device__ __forceinline__ unsigned f2tf32(float x) {
    unsigned y;
    asm("cvt.rna.tf32.f32 %0, %1;" : "=r"(y) : "f"(x));
    return y;
}
__device__ __forceinline__ float round_tf32(float x) {
    return __uint_as_float(f2tf32(x));
}
__device__ __forceinline__ float tanh_mufu(float x) {
    float y;
    asm("tanh.approx.f32 %0, %1;" : "=f"(y) : "f"(x));
    return y;
}
__device__ __forceinline__ void mma_tf32(float* c, const unsigned* a, const unsigned* b) {
    asm volatile(
        "mma.sync.aligned.m16n8k8.row.col.f32.tf32.tf32.f32 "
        "{%0,%1,%2,%3},{%4,%5,%6,%7},{%8,%9},{%0,%1,%2,%3};"
        : "+f"(c[0]), "+f"(c[1]), "+f"(c[2]), "+f"(c[3])
        : "r"(a[0]), "r"(a[1]), "r"(a[2]), "r"(a[3]), "r"(b[0]), "r"(b[1]));
}
__device__ __forceinline__ void cp_async16(unsigned dst, const void* src) {
    asm volatile("cp.async.cg.shared.global [%0], [%1], 16;" :: "r"(dst), "l"(src));
}
__device__ __forceinline__ void cp_commit() {
    asm volatile("cp.async.commit_group;");
}
__device__ __forceinline__ void cp_wait1() {
    asm volatile("cp.async.wait_group 1;");
}
__device__ __forceinline__ void cp_wait0() {
    asm volatile("cp.async.wait_group 0;");
}

// ---------------- FFMA-only precise tanh (gate path only) ---------------------
__device__ __forceinline__ float tanh_fast(float x) {
    float y = fminf(fmaxf(x * 2.885390081777927f, -28.f), 28.f);
    float tt = y + 12582912.f;
    int   ik = __float_as_int(tt) - 0x4B400000;
    float f  = y - (tt - 12582912.f);
    float p  = 1.5403530393e-4f;
    p = fmaf(p, f, 1.3333558146e-3f);
    p = fmaf(p, f, 9.6181291076e-3f);
    p = fmaf(p, f, 5.5504108664e-2f);
    p = fmaf(p, f, 2.4022650696e-1f);
    p = fmaf(p, f, 6.9314718056e-1f);
    p = fmaf(p, f, 1.0f);
    float e = __int_as_float(__float_as_int(p) + (ik << 23));
    float d = e + 1.0f;
    float r = __int_as_float(0x7EF311C3 - __float_as_int(d));
    r = r * (2.0f - d * r);
    r = r * (2.0f - d * r);
    return (e - 1.0f) * r;
}

// ---------------- 256-thread 2-stage cp.async tf32 GEMM ----------------------
__device__ __forceinline__ void gemm_issue(
    unsigned a_base, unsigned b_base,
    const float* __restrict__ A, int lda,
    const float* __restrict__ Bm, int ldb,
    int n0, int kb, int tid)
{
#pragma unroll
    for (int i = 0; i < 2; i++) {
        int idx = tid + i * 256;
        int rr = idx >> 3, kq = idx & 7;
        cp_async16(a_base + (unsigned)((rr * 32 + ((kq ^ (rr & 7)) << 2)) * 4),
                   A + (size_t)rr * lda + kb + kq * 4);
    }
#pragma unroll
    for (int i = 0; i < 4; i++) {
        int idx = tid + i * 256;
        int rr = idx >> 3, kq = idx & 7;
        cp_async16(b_base + (unsigned)((rr * 32 + ((kq ^ (rr & 7)) << 2)) * 4),
                   Bm + (size_t)(n0 + rr) * ldb + kb + kq * 4);
    }
    cp_commit();
}

__device__ __forceinline__ void gemm_async_rt(
    const float* __restrict__ A, int lda,
    const float* __restrict__ Bm, int ldb,
    float* __restrict__ C, int ldc,
    int n0, int k0, int niter)
{
    __shared__ float As[2][64 * 32];
    __shared__ float Bs[2][128 * 32];

    const int tid  = threadIdx.x;
    const int lane = tid & 31;
    const int warp = tid >> 5;
    const int wm = warp >> 2;
    const int wn = warp & 3;
    const int fr = lane >> 2;
    const int fc = lane & 3;

    unsigned sA = (unsigned)__cvta_generic_to_shared(&As[0][0]);
    unsigned sB = (unsigned)__cvta_generic_to_shared(&Bs[0][0]);

    float acc[2][4][4];
#pragma unroll
    for (int mi = 0; mi < 2; mi++)
#pragma unroll
        for (int ni = 0; ni < 4; ni++)
#pragma unroll
            for (int j = 0; j < 4; j++) acc[mi][ni][j] = 0.f;

    gemm_issue(sA, sB, A, lda, Bm, ldb, n0, k0, tid);

    for (int it = 0; it < niter; it++) {
        if (it + 1 < niter) {
            int st = (it + 1) & 1;
            gemm_issue(sA + st * 64 * 32 * 4, sB + st * 128 * 32 * 4,
                       A, lda, Bm, ldb, n0, k0 + (it + 1) * 32, tid);
            cp_wait1();
        } else {
            cp_wait0();
        }
        __syncthreads();

        const unsigned* as = (const unsigned*)As[it & 1];
        const unsigned* bs = (const unsigned*)Bs[it & 1];
#pragma unroll
        for (int ks = 0; ks < 4; ks++) {
            unsigned afr[2][4], bfr[4][2];
#pragma unroll
            for (int mi = 0; mi < 2; mi++) {
                int r0 = wm * 32 + mi * 16 + fr;
                int r1 = r0 + 8;
                int g0 = ((ks * 2)     ^ (r0 & 7)) << 2;
                int g1 = ((ks * 2 + 1) ^ (r0 & 7)) << 2;
                afr[mi][0] = as[r0 * 32 + g0 + fc];
                afr[mi][1] = as[r1 * 32 + g0 + fc];
                afr[mi][2] = as[r0 * 32 + g1 + fc];
                afr[mi][3] = as[r1 * 32 + g1 + fc];
            }
#pragma unroll
            for (int ni = 0; ni < 4; ni++) {
                int nr = wn * 32 + ni * 8 + fr;
                int g0 = ((ks * 2)     ^ (nr & 7)) << 2;
                int g1 = ((ks * 2 + 1) ^ (nr & 7)) << 2;
                bfr[ni][0] = bs[nr * 32 + g0 + fc];
                bfr[ni][1] = bs[nr * 32 + g1 + fc];
            }
#pragma unroll
            for (int mi = 0; mi < 2; mi++)
#pragma unroll
                for (int ni = 0; ni < 4; ni++)
                    mma_tf32(acc[mi][ni], afr[mi], bfr[ni]);
        }
        __syncthreads();
    }

#pragma unroll
    for (int mi = 0; mi < 2; mi++) {
        int row = wm * 32 + mi * 16 + fr;
#pragma unroll
        for (int ni = 0; ni < 4; ni++) {
            int col = n0 + wn * 32 + ni * 8 + fc * 2;
            *(float2*)&C[(size_t)row * ldc + col] =
                make_float2(acc[mi][ni][0], acc[mi][ni][1]);
            *(float2*)&C[(size_t)(row + 8) * ldc + col] =
                make_float2(acc[mi][ni][2], acc[mi][ni][3]);
        }
    }
}

// ---------------- precompute GEMM kernel --------------------------------------
__global__ __launch_bounds__(256) void gemm_pre2(
    const float* __restrict__ A, int lda,
    const float* __restrict__ Bm, int ldb,
    float* __restrict__ C, int ldc, int niter) {
    gemm_async_rt(A + (size_t)blockIdx.y * 64 * lda, lda, Bm, ldb,
                  C + (size_t)blockIdx.y * 64 * ldc, ldc,
                  blockIdx.x * 128, 0, niter);
}

// ---------------- ctxproj -> bf16 conversion -----------------------------------
__global__ void k_cvt_bf() {
    int stride = gridDim.x * blockDim.x;
    for (int i = blockIdx.x * blockDim.x + threadIdx.x;
         i < B * L * H / 2; i += stride) {
        float2 x = ((const float2*)g_ctxproj)[i];
        ((__nv_bfloat162*)g_cpbf)[i] = __float22bfloat162_rn(x);
    }
}

// ---------------- prep ---------------------------------------------------------
__global__ void k_prep(const float* __restrict__ h0,
                       const float* __restrict__ Wq,
                       const float* __restrict__ W_hh,
                       const float* __restrict__ W_ih,
                       const float* __restrict__ Wc,
                       const float* __restrict__ ctx) {
    int stride = gridDim.x * blockDim.x;
    int tid0 = blockIdx.x * blockDim.x + threadIdx.x;
    for (int i = tid0; i < BH; i += stride) {
        float h = h0[i];
        g_h[i] = h;
        g_hr[i] = round_tf32(h);
    }
    for (int i = tid0; i < H * H; i += stride)
        g_Wq[i] = round_tf32(Wq[i]);
    for (int i = tid0; i < G3 * H; i += stride)
        g_Whh[i] = round_tf32(W_hh[i]);
    for (size_t i = tid0; i < (size_t)G3 * CDIM; i += stride) {
        size_t r = i / CDIM, c = i - r * CDIM;
        g_Wihc[i] = round_tf32(W_ih[r * XK + E + c]);
    }
    for (size_t i = tid0; i < (size_t)G3 * E; i += stride) {
        size_t r = i / E, c = i - r * E;
        g_Wihe[i] = round_tf32(W_ih[r * XK + c]);
    }
    for (size_t i = tid0; i < (size_t)H * CDIM; i += stride)
        g_Wcr[i] = round_tf32(Wc[i]);
    for (size_t i = tid0; i < (size_t)B * L * CDIM; i += stride)
        g_ctxr[i] = round_tf32(ctx[i]);
}

// ---------------- embedding gather ---------------------------------------------
__global__ void k_emb(const int* __restrict__ tgt,
                      const float* __restrict__ emb,
                      float* __restrict__ out) {
    int row = blockIdx.x;
    int tok = tgt[row];
    float4 s = ((const float4*)(emb + (size_t)tok * E))[threadIdx.x];
    ((float4*)(out + (size_t)row * OC + H))[threadIdx.x] = s;
    float4 r = {round_tf32(s.x), round_tf32(s.y), round_tf32(s.z), round_tf32(s.w)};
    ((float4*)(g_xemb + (size_t)row * E))[threadIdx.x] = r;
}

// ---------------- K1: q partials (64 blk) ---------------------------------------
__global__ __launch_bounds__(256) void k1_q() {
    pdl_wait();
    int nt = blockIdx.x & 7, ks = blockIdx.x >> 3;   // kc = 128
    gemm_async_rt(g_hr, H, g_Wq, H, g_qpart + ks * BH, H, nt * 128, ks * 128, 4);
    pdl_launch_dep();
}

// ---------------- K2: attention only (128 blk, 2 per batch) ---------------------
__global__ __launch_bounds__(1024) void k2_attn(
    const float* __restrict__ ctx,
    const float* __restrict__ bq,
    const float* __restrict__ v,
    float* __restrict__ out, int t)
{
    const int tid = threadIdx.x;
    __shared__ float pool[5184];     // s_q 1024 | s_v 1024 | s_attn 64 | s_part 768*f4

    const int b = blockIdx.x >> 1;
    const int half = blockIdx.x & 1;
    float*  s_q    = pool;                       // 1024
    float*  s_v    = pool + 1024;                // 1024
    float*  s_attn = pool + 2048;                // 64
    float4* s_part = (float4*)(pool + 2112);     // 768 float4

    pdl_wait();

    // q-partial reduction: 512 threads (2 groups of 4 partials), +bq in group 0
    if (tid < 512) {
        int c4 = tid & 255, grp = tid >> 8;
        float4 q = (grp == 0) ? ((const float4*)bq)[c4]
                              : make_float4(0.f, 0.f, 0.f, 0.f);
#pragma unroll
        for (int p = 0; p < 4; p++) {
            float4 qp = ((const float4*)(g_qpart + (grp * 4 + p) * BH + b * H))[c4];
            q.x += qp.x; q.y += qp.y; q.z += qp.z; q.w += qp.w;
        }
        s_part[tid] = q;
    } else if (tid < 768) {
        ((float4*)s_v)[tid - 512] = ((const float4*)v)[tid - 512];
    }
    __syncthreads();
    if (tid < 256) {
        float4 a = s_part[tid], c = s_part[tid + 256];
        ((float4*)s_q)[tid] = make_float4(a.x + c.x, a.y + c.y, a.z + c.z, a.w + c.w);
    }
    __syncthreads();

    // scores via MUFU tanh on bf16 ctxproj: 32 warps, 2 rows each
    {
        const int w = tid >> 5, lane = tid & 31;
#pragma unroll
        for (int rep = 0; rep < 2; rep++) {
            int l = w + rep * 32;
            const __nv_bfloat162* cp =
                (const __nv_bfloat162*)(g_cpbf + ((size_t)(b * L + l)) * H);
            float acc = 0.f;
#pragma unroll
            for (int j = 0; j < 16; j++) {
                int c2 = j * 32 + lane;
                float2 c = __bfloat1622float2(cp[c2]);
                float2 q = ((const float2*)s_q)[c2];
                float2 vv = ((const float2*)s_v)[c2];
                acc += vv.x * tanh_mufu(c.x + q.x) + vv.y * tanh_mufu(c.y + q.y);
            }
#pragma unroll
            for (int o = 16; o; o >>= 1) acc += __shfl_xor_sync(0xffffffffu, acc, o);
            if (lane == 0) s_attn[l] = acc;
        }
    }
    __syncthreads();

    // softmax (warp 0)
    if (tid < 32) {
        float s0 = s_attn[tid], s1 = s_attn[tid + 32];
        float m = fmaxf(s0, s1);
#pragma unroll
        for (int o = 16; o; o >>= 1) m = fmaxf(m, __shfl_xor_sync(0xffffffffu, m, o));
        float e0 = __expf(s0 - m), e1 = __expf(s1 - m);
        float ss = e0 + e1;
#pragma unroll
        for (int o = 16; o; o >>= 1) ss += __shfl_xor_sync(0xffffffffu, ss, o);
        s_attn[tid] = e0 / ss; s_attn[tid + 32] = e1 / ss;
    }
    __syncthreads();

    // ctx_t for this block's half (1024 cols): 4 threads per float4-col, 16 rows each
    {
        const int c4l = tid & 255;                 // 0..255 within half
        const int piece = tid >> 8;                // 0..3
        const int c4 = half * 256 + c4l;           // global float4 col
        const float4* cb4 = (const float4*)(ctx + (size_t)b * L * CDIM);
        float4 acc = {0.f, 0.f, 0.f, 0.f};
        const int l0 = piece * 16;
#pragma unroll 8
        for (int l = l0; l < l0 + 16; l++) {
            float a = s_attn[l];
            float4 x = cb4[(size_t)l * (CDIM / 4) + c4];
            acc.x = fmaf(a, x.x, acc.x); acc.y = fmaf(a, x.y, acc.y);
            acc.z = fmaf(a, x.z, acc.z); acc.w = fmaf(a, x.w, acc.w);
        }
        if (piece > 0) s_part[(piece - 1) * 256 + c4l] = acc;
        __syncthreads();
        if (piece == 0) {
            float4 p1 = s_part[c4l];
            float4 p2 = s_part[256 + c4l];
            float4 p3 = s_part[512 + c4l];
            acc.x += p1.x + p2.x + p3.x;
            acc.y += p1.y + p2.y + p3.y;
            acc.z += p1.z + p2.z + p3.z;
            acc.w += p1.w + p2.w + p3.w;
            ((float4*)(out + ((size_t)(b * S + t)) * OC + H + E))[c4] = acc;
            float4 rr = {round_tf32(acc.x), round_tf32(acc.y),
                         round_tf32(acc.z), round_tf32(acc.w)};
            ((float4*)(g_ctxt + (size_t)b * CDIM))[c4] = rr;
        }
    }
    pdl_launch_dep();
}

// ---------------- K3: gi partials (blk 0-191) + gh partials (blk 192-287) -------
__global__ __launch_bounds__(256) void k3_gates() {
    pdl_wait();
    int bid = blockIdx.x;
    if (bid < 192) {
        int nt = bid % 24, ks = bid / 24;             // ks 0..7, kc=256
        gemm_async_rt(g_ctxt, CDIM, g_Wihc, CDIM,
                      g_gipart + (size_t)ks * BG3, G3, nt * 128, ks * 256, 8);
    } else {
        int u = bid - 192;
        int nt = u % 24, ks = u / 24;                  // ks 0..3, kc=256
        gemm_async_rt(g_hr, H, g_Whh, H,
                      g_ghpart + (size_t)ks * BG3, G3, nt * 128, ks * 256, 8);
    }
    pdl_launch_dep();
}

// ---------------- K4: GRU update ------------------------------------------------
__global__ __launch_bounds__(256) void k4_update(
    const float* __restrict__ b_ih, const float* __restrict__ b_hh,
    float* __restrict__ out, int t)
{
    const int idx = blockIdx.x * 256 + threadIdx.x;
    const int b = idx >> 10, i = idx & (H - 1);
    const size_t ge = ((size_t)(b * S + t)) * G3;

    pdl_wait();

    float ir  = b_ih[i]         + g_giemb[ge + i];
    float iz  = b_ih[H + i]     + g_giemb[ge + H + i];
    float in_ = b_ih[2 * H + i] + g_giemb[ge + 2 * H + i];
#pragma unroll
    for (int p = 0; p < 8; p++) {
        const float* gp = g_gipart + (size_t)p * BG3 + (size_t)b * G3;
        ir += gp[i]; iz += gp[H + i]; in_ += gp[2 * H + i];
    }
    float hr = b_hh[i], hz = b_hh[H + i], hn = b_hh[2 * H + i];
#pragma unroll
    for (int p = 0; p < 4; p++) {
        const float* gp = g_ghpart + (size_t)p * BG3 + (size_t)b * G3;
        hr += gp[i]; hz += gp[H + i]; hn += gp[2 * H + i];
    }
    float r = 1.f / (1.f + __expf(-(ir + hr)));
    float z = 1.f / (1.f + __expf(-(iz + hz)));
    float n = tanh_fast(in_ + r * hn);
    float hold = g_h[idx];
    float hnew = (1.f - z) * n + z * hold;

    g_h[idx]  = hnew;
    g_hr[idx] = round_tf32(hnew);
    out[((size_t)(b * S + t)) * OC + i] = hold;
    if (t == S - 1)
        out[(size_t)B * S * OC + idx] = hnew;

    pdl_launch_dep();
}

// -----------------------------------------------------------------------------
template <typename... Args>
static inline void launch_pdl(void (*kern)(Args...), dim3 grid, dim3 blk,
                              Args... args) {
    cudaLaunchConfig_t cfg = {};
    cfg.gridDim = grid;
    cfg.blockDim = blk;
    cfg.dynamicSmemBytes = 0;
    cfg.stream = 0;
    cudaLaunchAttribute attr[1];
    attr[0].id = cudaLaunchAttributeProgrammaticStreamSerialization;
    attr[0].val.programmaticStreamSerializationAllowed = 1;
    cfg.attrs = attr;
    cfg.numAttrs = 1;
    cudaLaunchKernelEx(&cfg, kern, args...);
}

extern "C" void kernel_launch(void* const* d_in, const int* in_sizes, int n_in,
                              void* d_out, int out_size) {
    const int*   tgt  = (const int*)d_in[0];
    const float* ctx  = (const float*)d_in[1];
    const float* h0   = (const float*)d_in[2];
    const float* emb  = (const float*)d_in[3];
    const float* Wc   = (const float*)d_in[4];
    const float* Wq   = (const float*)d_in[5];
    const float* bq   = (const float*)d_in[6];
    const float* v    = (const float*)d_in[7];
    const float* W_ih = (const float*)d_in[8];
    const float* W_hh = (const float*)d_in[9];
    const float* b_ih = (const float*)d_in[10];
    const float* b_hh = (const float*)d_in[11];
    float* out = (float*)d_out;

    float *p_cp, *p_ge, *p_cr, *p_wcr, *p_xe, *p_wihe;
    cudaGetSymbolAddress((void**)&p_cp,   g_ctxproj);
    cudaGetSymbolAddress((void**)&p_ge,   g_giemb);
    cudaGetSymbolAddress((void**)&p_cr,   g_ctxr);
    cudaGetSymbolAddress((void**)&p_wcr,  g_Wcr);
    cudaGetSymbolAddress((void**)&p_xe,   g_xemb);
    cudaGetSymbolAddress((void**)&p_wihe, g_Wihe);

    k_prep<<<1024, 256>>>(h0, Wq, W_hh, W_ih, Wc, ctx);
    k_emb<<<B * S, 128>>>(tgt, emb, out);

    // ctx_proj[B*L, H] = ctxR @ WcR^T
    gemm_pre2<<<dim3(H / 128, (B * L) / 64), 256>>>(p_cr, CDIM, p_wcr, CDIM, p_cp, H, 64);
    // bf16 copy of ctx_proj for the scores path
    k_cvt_bf<<<1024, 256>>>();
    // gi_emb[B*S, 3H] = embR @ WiheR^T
    gemm_pre2<<<dim3(G3 / 128, (B * S) / 64), 256>>>(p_xe, E, p_wihe, E, p_ge, G3, 16);

    for (int t = 0; t < S; t++) {
        launch_pdl(k1_q, dim3(64), dim3(256));
        launch_pdl(k2_attn, dim3(128), dim3(1024), ctx, bq, v, out, t);
        launch_pdl(k3_gates, dim3(288), dim3(256));
        launch_pdl(k4_update, dim3(BH / 256), dim3(256), b_ih, b_hh, out, t);
    }
}

// round 13
// speedup vs baseline: 1.4869x; 1.0065x over previous
#include <cuda_runtime.h>
#include <cuda_bf16.h>
#include <math.h>

#define B 64
#define S 64
#define L 64
#define H 1024
#define CDIM 2048
#define E 512
#define OC (H + E + CDIM)   // 3584
#define XK (E + CDIM)       // 2560
#define G3 (3 * H)          // 3072
#define BH (B * H)
#define BG3 (B * G3)

// ---------------- scratch (device globals) ----------------------------------
__device__ float g_ctxproj[B * L * H];
__device__ __nv_bfloat16 g_cpbf[B * L * H];
__device__ float g_giemb[(size_t)B * S * G3];
__device__ float g_h[BH];
__device__ float g_hr[BH];
__device__ float g_ctxt[B * CDIM];
__device__ float g_qpart[8 * BH];
__device__ float g_gipart[8 * (size_t)BG3];
__device__ float g_ghpart[4 * (size_t)BG3];
__device__ unsigned g_cntA;     // monotonic producer counters
__device__ unsigned g_cntB;
// pre-rounded weights / operands
__device__ float g_Wq[H * H];
__device__ float g_Whh[G3 * H];
__device__ float g_Wihc[(size_t)G3 * CDIM];
__device__ float g_Wihe[G3 * E];
__device__ float g_Wcr[H * CDIM];
__device__ float g_ctxr[B * L * CDIM];
__device__ float g_xemb[B * S * E];

// ---------------- PDL helpers --------------------------------------------------
__device__ __forceinline__ void pdl_wait() {
    asm volatile("griddepcontrol.wait;" ::: "memory");
}
__device__ __forceinline__ void pdl_launch_dep() {
    asm volatile("griddepcontrol.launch_dependents;" ::: "memory");
}

// ---------------- helpers ----------------------------------------------------
__device__ __forceinline__ unsigned f2tf32(float x) {
    unsigned y;
    asm("cvt.rna.tf32.f32 %0, %1;" : "=r"(y) : "f"(x));
    return y;
}
__device__ __forceinline__ float round_tf32(float x) {
    return __uint_as_float(f2tf32(x));
}
__device__ __forceinline__ float tanh_mufu(float x) {
    float y;
    asm("tanh.approx.f32 %0, %1;" : "=f"(y) : "f"(x));
    return y;
}
__device__ __forceinline__ void mma_tf32(float* c, const unsigned* a, const unsigned* b) {
    asm volatile(
        "mma.sync.aligned.m16n8k8.row.col.f32.tf32.tf32.f32 "
        "{%0,%1,%2,%3},{%4,%5,%6,%7},{%8,%9},{%0,%1,%2,%3};"
        : "+f"(c[0]), "+f"(c[1]), "+f"(c[2]), "+f"(c[3])
        : "r"(a[0]), "r"(a[1]), "r"(a[2]), "r"(a[3]), "r"(b[0]), "r"(b[1]));
}
__device__ __forceinline__ void cp_async16(unsigned dst, const void* src) {
    asm volatile("cp.async.cg.shared.global [%0], [%1], 16;" :: "r"(dst), "l"(src));
}
__device__ __forceinline__ void cp_commit() {
    asm volatile("cp.async.commit_group;");
}
__device__ __forceinline__ void cp_wait1() {
    asm volatile("cp.async.wait_group 1;");
}
__device__ __forceinline__ void cp_wait0() {
    asm volatile("cp.async.wait_group 0;");
}

// producer: all threads' stores done -> count
__device__ __forceinline__ void flag_arrive(unsigned* cnt) {
    __syncthreads();
    __threadfence();
    if (threadIdx.x == 0) atomicAdd(cnt, 1u);
}
// consumer: wait until cnt >= target
__device__ __forceinline__ void flag_wait(unsigned* cnt, unsigned target) {
    if (threadIdx.x == 0) {
        volatile unsigned* c = (volatile unsigned*)cnt;
        while (*c < target) { __nanosleep(32); }
        __threadfence();
    }
    __syncthreads();
}

// ---------------- FFMA-only precise tanh (gate path only) ---------------------
__device__ __forceinline__ float tanh_fast(float x) {
    float y = fminf(fmaxf(x * 2.885390081777927f, -28.f), 28.f);
    float tt = y + 12582912.f;
    int   ik = __float_as_int(tt) - 0x4B400000;
    float f  = y - (tt - 12582912.f);
    float p  = 1.5403530393e-4f;
    p = fmaf(p, f, 1.3333558146e-3f);
    p = fmaf(p, f, 9.6181291076e-3f);
    p = fmaf(p, f, 5.5504108664e-2f);
    p = fmaf(p, f, 2.4022650696e-1f);
    p = fmaf(p, f, 6.9314718056e-1f);
    p = fmaf(p, f, 1.0f);
    float e = __int_as_float(__float_as_int(p) + (ik << 23));
    float d = e + 1.0f;
    float r = __int_as_float(0x7EF311C3 - __float_as_int(d));
    r = r * (2.0f - d * r);
    r = r * (2.0f - d * r);
    return (e - 1.0f) * r;
}

// ---------------- 256-thread 2-stage cp.async tf32 GEMM ----------------------
__device__ __forceinline__ void gemm_issue(
    unsigned a_base, unsigned b_base,
    const float* __restrict__ A, int lda,
    const float* __restrict__ Bm, int ldb,
    int n0, int kb, int tid)
{
#pragma unroll
    for (int i = 0; i < 2; i++) {
        int idx = tid + i * 256;
        int rr = idx >> 3, kq = idx & 7;
        cp_async16(a_base + (unsigned)((rr * 32 + ((kq ^ (rr & 7)) << 2)) * 4),
                   A + (size_t)rr * lda + kb + kq * 4);
    }
#pragma unroll
    for (int i = 0; i < 4; i++) {
        int idx = tid + i * 256;
        int rr = idx >> 3, kq = idx & 7;
        cp_async16(b_base + (unsigned)((rr * 32 + ((kq ^ (rr & 7)) << 2)) * 4),
                   Bm + (size_t)(n0 + rr) * ldb + kb + kq * 4);
    }
    cp_commit();
}

__device__ __forceinline__ void gemm_async_rt(
    const float* __restrict__ A, int lda,
    const float* __restrict__ Bm, int ldb,
    float* __restrict__ C, int ldc,
    int n0, int k0, int niter)
{
    __shared__ float As[2][64 * 32];
    __shared__ float Bs[2][128 * 32];

    const int tid  = threadIdx.x;
    const int lane = tid & 31;
    const int warp = tid >> 5;
    const int wm = warp >> 2;
    const int wn = warp & 3;
    const int fr = lane >> 2;
    const int fc = lane & 3;

    unsigned sA = (unsigned)__cvta_generic_to_shared(&As[0][0]);
    unsigned sB = (unsigned)__cvta_generic_to_shared(&Bs[0][0]);

    float acc[2][4][4];
#pragma unroll
    for (int mi = 0; mi < 2; mi++)
#pragma unroll
        for (int ni = 0; ni < 4; ni++)
#pragma unroll
            for (int j = 0; j < 4; j++) acc[mi][ni][j] = 0.f;

    gemm_issue(sA, sB, A, lda, Bm, ldb, n0, k0, tid);

    for (int it = 0; it < niter; it++) {
        if (it + 1 < niter) {
            int st = (it + 1) & 1;
            gemm_issue(sA + st * 64 * 32 * 4, sB + st * 128 * 32 * 4,
                       A, lda, Bm, ldb, n0, k0 + (it + 1) * 32, tid);
            cp_wait1();
        } else {
            cp_wait0();
        }
        __syncthreads();

        const unsigned* as = (const unsigned*)As[it & 1];
        const unsigned* bs = (const unsigned*)Bs[it & 1];
#pragma unroll
        for (int ks = 0; ks < 4; ks++) {
            unsigned afr[2][4], bfr[4][2];
#pragma unroll
            for (int mi = 0; mi < 2; mi++) {
                int r0 = wm * 32 + mi * 16 + fr;
                int r1 = r0 + 8;
                int g0 = ((ks * 2)     ^ (r0 & 7)) << 2;
                int g1 = ((ks * 2 + 1) ^ (r0 & 7)) << 2;
                afr[mi][0] = as[r0 * 32 + g0 + fc];
                afr[mi][1] = as[r1 * 32 + g0 + fc];
                afr[mi][2] = as[r0 * 32 + g1 + fc];
                afr[mi][3] = as[r1 * 32 + g1 + fc];
            }
#pragma unroll
            for (int ni = 0; ni < 4; ni++) {
                int nr = wn * 32 + ni * 8 + fr;
                int g0 = ((ks * 2)     ^ (nr & 7)) << 2;
                int g1 = ((ks * 2 + 1) ^ (nr & 7)) << 2;
                bfr[ni][0] = bs[nr * 32 + g0 + fc];
                bfr[ni][1] = bs[nr * 32 + g1 + fc];
            }
#pragma unroll
            for (int mi = 0; mi < 2; mi++)
#pragma unroll
                for (int ni = 0; ni < 4; ni++)
                    mma_tf32(acc[mi][ni], afr[mi], bfr[ni]);
        }
        __syncthreads();
    }

#pragma unroll
    for (int mi = 0; mi < 2; mi++) {
        int row = wm * 32 + mi * 16 + fr;
#pragma unroll
        for (int ni = 0; ni < 4; ni++) {
            int col = n0 + wn * 32 + ni * 8 + fc * 2;
            *(float2*)&C[(size_t)row * ldc + col] =
                make_float2(acc[mi][ni][0], acc[mi][ni][1]);
            *(float2*)&C[(size_t)(row + 8) * ldc + col] =
                make_float2(acc[mi][ni][2], acc[mi][ni][3]);
        }
    }
}

// ---------------- 1024-thread GEMM tile (pool smem) ---------------------------
__device__ __forceinline__ void gemm_issue1024(
    unsigned a_base, unsigned b_base,
    const float* __restrict__ A, int lda,
    const float* __restrict__ Bm, int ldb,
    int n0, int kb, int tid)
{
    if (tid < 512) {
        int rr = tid >> 3, kq = tid & 7;
        cp_async16(a_base + (unsigned)((rr * 32 + ((kq ^ (rr & 7)) << 2)) * 4),
                   A + (size_t)rr * lda + kb + kq * 4);
    }
    int rr = tid >> 3, kq = tid & 7;
    cp_async16(b_base + (unsigned)((rr * 32 + ((kq ^ (rr & 7)) << 2)) * 4),
               Bm + (size_t)(n0 + rr) * ldb + kb + kq * 4);
    cp_commit();
}

template <int NITER>
__device__ __forceinline__ void gemm_async1024_pool(
    float* pool,
    const float* __restrict__ A, int lda,
    const float* __restrict__ Bm, int ldb,
    float* __restrict__ C, int ldc,
    int n0, int k0)
{
    float* As2 = pool;
    float* Bs2 = pool + 2 * 64 * 32;

    const int tid  = threadIdx.x;
    const int lane = tid & 31;
    const int warp = tid >> 5;       // 0..31
    const int wm = warp >> 4;        // 0..1
    const int wn = warp & 15;        // 0..15
    const int fr = lane >> 2;
    const int fc = lane & 3;

    unsigned sA = (unsigned)__cvta_generic_to_shared(As2);
    unsigned sB = (unsigned)__cvta_generic_to_shared(Bs2);

    float acc[2][4];
#pragma unroll
    for (int mi = 0; mi < 2; mi++)
#pragma unroll
        for (int j = 0; j < 4; j++) acc[mi][j] = 0.f;

    gemm_issue1024(sA, sB, A, lda, Bm, ldb, n0, k0, tid);

#pragma unroll
    for (int it = 0; it < NITER; it++) {
        if (it + 1 < NITER) {
            int st = (it + 1) & 1;
            gemm_issue1024(sA + st * 64 * 32 * 4, sB + st * 128 * 32 * 4,
                           A, lda, Bm, ldb, n0, k0 + (it + 1) * 32, tid);
            cp_wait1();
        } else {
            cp_wait0();
        }
        __syncthreads();

        const unsigned* as = (const unsigned*)(As2 + (it & 1) * 64 * 32);
        const unsigned* bs = (const unsigned*)(Bs2 + (it & 1) * 128 * 32);
#pragma unroll
        for (int ks = 0; ks < 4; ks++) {
            unsigned afr[2][4], bfr[2];
#pragma unroll
            for (int mi = 0; mi < 2; mi++) {
                int r0 = wm * 32 + mi * 16 + fr;
                int r1 = r0 + 8;
                int g0 = ((ks * 2)     ^ (r0 & 7)) << 2;
                int g1 = ((ks * 2 + 1) ^ (r0 & 7)) << 2;
                afr[mi][0] = as[r0 * 32 + g0 + fc];
                afr[mi][1] = as[r1 * 32 + g0 + fc];
                afr[mi][2] = as[r0 * 32 + g1 + fc];
                afr[mi][3] = as[r1 * 32 + g1 + fc];
            }
            {
                int nr = wn * 8 + fr;
                int g0 = ((ks * 2)     ^ (nr & 7)) << 2;
                int g1 = ((ks * 2 + 1) ^ (nr & 7)) << 2;
                bfr[0] = bs[nr * 32 + g0 + fc];
                bfr[1] = bs[nr * 32 + g1 + fc];
            }
#pragma unroll
            for (int mi = 0; mi < 2; mi++)
                mma_tf32(acc[mi], afr[mi], bfr);
        }
        __syncthreads();
    }

#pragma unroll
    for (int mi = 0; mi < 2; mi++) {
        int row = wm * 32 + mi * 16 + fr;
        int col = n0 + wn * 8 + fc * 2;
        *(float2*)&C[(size_t)row * ldc + col] = make_float2(acc[mi][0], acc[mi][1]);
        *(float2*)&C[(size_t)(row + 8) * ldc + col] = make_float2(acc[mi][2], acc[mi][3]);
    }
}

// ---------------- precompute GEMM kernel --------------------------------------
__global__ __launch_bounds__(256) void gemm_pre2(
    const float* __restrict__ A, int lda,
    const float* __restrict__ Bm, int ldb,
    float* __restrict__ C, int ldc, int niter) {
    gemm_async_rt(A + (size_t)blockIdx.y * 64 * lda, lda, Bm, ldb,
                  C + (size_t)blockIdx.y * 64 * ldc, ldc,
                  blockIdx.x * 128, 0, niter);
}

// ---------------- ctxproj -> bf16 conversion -----------------------------------
__global__ void k_cvt_bf() {
    int stride = gridDim.x * blockDim.x;
    for (int i = blockIdx.x * blockDim.x + threadIdx.x;
         i < B * L * H / 2; i += stride) {
        float2 x = ((const float2*)g_ctxproj)[i];
        ((__nv_bfloat162*)g_cpbf)[i] = __float22bfloat162_rn(x);
    }
}

// ---------------- prep ---------------------------------------------------------
__global__ void k_prep(const float* __restrict__ h0,
                       const float* __restrict__ Wq,
                       const float* __restrict__ W_hh,
                       const float* __restrict__ W_ih,
                       const float* __restrict__ Wc,
                       const float* __restrict__ ctx) {
    int stride = gridDim.x * blockDim.x;
    int tid0 = blockIdx.x * blockDim.x + threadIdx.x;
    if (tid0 == 0) { g_cntA = 0; g_cntB = 0; }
    for (int i = tid0; i < BH; i += stride) {
        float h = h0[i];
        g_h[i] = h;
        g_hr[i] = round_tf32(h);
    }
    for (int i = tid0; i < H * H; i += stride)
        g_Wq[i] = round_tf32(Wq[i]);
    for (int i = tid0; i < G3 * H; i += stride)
        g_Whh[i] = round_tf32(W_hh[i]);
    for (size_t i = tid0; i < (size_t)G3 * CDIM; i += stride) {
        size_t r = i / CDIM, c = i - r * CDIM;
        g_Wihc[i] = round_tf32(W_ih[r * XK + E + c]);
    }
    for (size_t i = tid0; i < (size_t)G3 * E; i += stride) {
        size_t r = i / E, c = i - r * E;
        g_Wihe[i] = round_tf32(W_ih[r * XK + c]);
    }
    for (size_t i = tid0; i < (size_t)H * CDIM; i += stride)
        g_Wcr[i] = round_tf32(Wc[i]);
    for (size_t i = tid0; i < (size_t)B * L * CDIM; i += stride)
        g_ctxr[i] = round_tf32(ctx[i]);
}

// ---------------- embedding gather ---------------------------------------------
__global__ void k_emb(const int* __restrict__ tgt,
                      const float* __restrict__ emb,
                      float* __restrict__ out) {
    int row = blockIdx.x;
    int tok = tgt[row];
    float4 s = ((const float4*)(emb + (size_t)tok * E))[threadIdx.x];
    ((float4*)(out + (size_t)row * OC + H))[threadIdx.x] = s;
    float4 r = {round_tf32(s.x), round_tf32(s.y), round_tf32(s.z), round_tf32(s.w)};
    ((float4*)(g_xemb + (size_t)row * E))[threadIdx.x] = r;
}

// ---------------- KA: q GEMM (blk 0-63) + attention (blk 64-191) ----------------
__global__ __launch_bounds__(1024) void kA(
    const float* __restrict__ ctx,
    const float* __restrict__ bq,
    const float* __restrict__ v,
    float* __restrict__ out, int t)
{
    const int tid = threadIdx.x;
    __shared__ float pool[12288];    // 48 KB, aliased by both paths

    if (blockIdx.x < 64) {
        // ---- q producers: qpart[ks] tile (kc=128, NITER=4)
        pdl_wait();
        int nt = blockIdx.x & 7, ks = blockIdx.x >> 3;
        gemm_async1024_pool<4>(pool, g_hr, H, g_Wq, H,
                               g_qpart + ks * BH, H, nt * 128, ks * 128);
        flag_arrive(&g_cntA);
        pdl_launch_dep();
        return;
    }

    // ---- attention consumers (2 blocks per batch)
    const int u = blockIdx.x - 64;
    const int b = u >> 1;
    const int half = u & 1;
    float*  s_q    = pool;
    float*  s_v    = pool + 1024;
    float*  s_attn = pool + 2048;
    float4* s_part = (float4*)(pool + 2112);

    pdl_wait();
    flag_wait(&g_cntA, 64u * (unsigned)(t + 1));

    // q-partial reduction: 512 threads (2 groups of 4 partials), +bq in group 0
    if (tid < 512) {
        int c4 = tid & 255, grp = tid >> 8;
        float4 q = (grp == 0) ? ((const float4*)bq)[c4]
                              : make_float4(0.f, 0.f, 0.f, 0.f);
#pragma unroll
        for (int p = 0; p < 4; p++) {
            float4 qp = ((const float4*)(g_qpart + (grp * 4 + p) * BH + b * H))[c4];
            q.x += qp.x; q.y += qp.y; q.z += qp.z; q.w += qp.w;
        }
        s_part[tid] = q;
    } else if (tid < 768) {
        ((float4*)s_v)[tid - 512] = ((const float4*)v)[tid - 512];
    }
    __syncthreads();
    if (tid < 256) {
        float4 a = s_part[tid], c = s_part[tid + 256];
        ((float4*)s_q)[tid] = make_float4(a.x + c.x, a.y + c.y, a.z + c.z, a.w + c.w);
    }
    __syncthreads();

    // scores via MUFU tanh on bf16 ctxproj: 32 warps, 2 rows each
    {
        const int w = tid >> 5, lane = tid & 31;
#pragma unroll
        for (int rep = 0; rep < 2; rep++) {
            int l = w + rep * 32;
            const __nv_bfloat162* cp =
                (const __nv_bfloat162*)(g_cpbf + ((size_t)(b * L + l)) * H);
            float acc = 0.f;
#pragma unroll
            for (int j = 0; j < 16; j++) {
                int c2 = j * 32 + lane;
                float2 c = __bfloat1622float2(cp[c2]);
                float2 q = ((const float2*)s_q)[c2];
                float2 vv = ((const float2*)s_v)[c2];
                acc += vv.x * tanh_mufu(c.x + q.x) + vv.y * tanh_mufu(c.y + q.y);
            }
#pragma unroll
            for (int o = 16; o; o >>= 1) acc += __shfl_xor_sync(0xffffffffu, acc, o);
            if (lane == 0) s_attn[l] = acc;
        }
    }
    __syncthreads();

    // softmax (warp 0)
    if (tid < 32) {
        float s0 = s_attn[tid], s1 = s_attn[tid + 32];
        float m = fmaxf(s0, s1);
#pragma unroll
        for (int o = 16; o; o >>= 1) m = fmaxf(m, __shfl_xor_sync(0xffffffffu, m, o));
        float e0 = __expf(s0 - m), e1 = __expf(s1 - m);
        float ss = e0 + e1;
#pragma unroll
        for (int o = 16; o; o >>= 1) ss += __shfl_xor_sync(0xffffffffu, ss, o);
        s_attn[tid] = e0 / ss; s_attn[tid + 32] = e1 / ss;
    }
    __syncthreads();

    // ctx_t half (1024 cols): 4 threads per float4-col, 16 rows each
    {
        const int c4l = tid & 255;
        const int piece = tid >> 8;
        const int c4 = half * 256 + c4l;
        const float4* cb4 = (const float4*)(ctx + (size_t)b * L * CDIM);
        float4 acc = {0.f, 0.f, 0.f, 0.f};
        const int l0 = piece * 16;
#pragma unroll 8
        for (int l = l0; l < l0 + 16; l++) {
            float a = s_attn[l];
            float4 x = cb4[(size_t)l * (CDIM / 4) + c4];
            acc.x = fmaf(a, x.x, acc.x); acc.y = fmaf(a, x.y, acc.y);
            acc.z = fmaf(a, x.z, acc.z); acc.w = fmaf(a, x.w, acc.w);
        }
        if (piece > 0) s_part[(piece - 1) * 256 + c4l] = acc;
        __syncthreads();
        if (piece == 0) {
            float4 p1 = s_part[c4l];
            float4 p2 = s_part[256 + c4l];
            float4 p3 = s_part[512 + c4l];
            acc.x += p1.x + p2.x + p3.x;
            acc.y += p1.y + p2.y + p3.y;
            acc.z += p1.z + p2.z + p3.z;
            acc.w += p1.w + p2.w + p3.w;
            ((float4*)(out + ((size_t)(b * S + t)) * OC + H + E))[c4] = acc;
            float4 rr = {round_tf32(acc.x), round_tf32(acc.y),
                         round_tf32(acc.z), round_tf32(acc.w)};
            ((float4*)(g_ctxt + (size_t)b * CDIM))[c4] = rr;
        }
    }
    pdl_launch_dep();
}

// ---------------- KB: gi (0-191) + gh (192-287) GEMMs, update (288-543) ---------
__global__ __launch_bounds__(256) void kB(
    const float* __restrict__ b_ih, const float* __restrict__ b_hh,
    float* __restrict__ out, int t)
{
    const int bid = blockIdx.x;

    if (bid < 288) {
        pdl_wait();
        if (bid < 192) {
            int nt = bid % 24, ks = bid / 24;             // ks 0..7, kc=256
            gemm_async_rt(g_ctxt, CDIM, g_Wihc, CDIM,
                          g_gipart + (size_t)ks * BG3, G3, nt * 128, ks * 256, 8);
        } else {
            int u = bid - 192;
            int nt = u % 24, ks = u / 24;                  // ks 0..3, kc=256
            gemm_async_rt(g_hr, H, g_Whh, H,
                          g_ghpart + (size_t)ks * BG3, G3, nt * 128, ks * 256, 8);
        }
        flag_arrive(&g_cntB);
        pdl_launch_dep();
        return;
    }

    // ---- GRU update consumers (256 blocks)
    const int idx = (bid - 288) * 256 + threadIdx.x;
    const int b = idx >> 10, i = idx & (H - 1);
    const size_t ge = ((size_t)(b * S + t)) * G3;

    pdl_wait();
    flag_wait(&g_cntB, 288u * (unsigned)(t + 1));

    float ir  = b_ih[i]         + g_giemb[ge + i];
    float iz  = b_ih[H + i]     + g_giemb[ge + H + i];
    float in_ = b_ih[2 * H + i] + g_giemb[ge + 2 * H + i];
#pragma unroll
    for (int p = 0; p < 8; p++) {
        const float* gp = g_gipart + (size_t)p * BG3 + (size_t)b * G3;
        ir += gp[i]; iz += gp[H + i]; in_ += gp[2 * H + i];
    }
    float hr = b_hh[i], hz = b_hh[H + i], hn = b_hh[2 * H + i];
#pragma unroll
    for (int p = 0; p < 4; p++) {
        const float* gp = g_ghpart + (size_t)p * BG3 + (size_t)b * G3;
        hr += gp[i]; hz += gp[H + i]; hn += gp[2 * H + i];
    }
    float r = 1.f / (1.f + __expf(-(ir + hr)));
    float z = 1.f / (1.f + __expf(-(iz + hz)));
    float n = tanh_fast(in_ + r * hn);
    float hold = g_h[idx];
    float hnew = (1.f - z) * n + z * hold;

    g_h[idx]  = hnew;
    g_hr[idx] = round_tf32(hnew);
    out[((size_t)(b * S + t)) * OC + i] = hold;
    if (t == S - 1)
        out[(size_t)B * S * OC + idx] = hnew;

    pdl_launch_dep();
}

// -----------------------------------------------------------------------------
template <typename... Args>
static inline void launch_pdl(void (*kern)(Args...), dim3 grid, dim3 blk,
                              Args... args) {
    cudaLaunchConfig_t cfg = {};
    cfg.gridDim = grid;
    cfg.blockDim = blk;
    cfg.dynamicSmemBytes = 0;
    cfg.stream = 0;
    cudaLaunchAttribute attr[1];
    attr[0].id = cudaLaunchAttributeProgrammaticStreamSerialization;
    attr[0].val.programmaticStreamSerializationAllowed = 1;
    cfg.attrs = attr;
    cfg.numAttrs = 1;
    cudaLaunchKernelEx(&cfg, kern, args...);
}

extern "C" void kernel_launch(void* const* d_in, const int* in_sizes, int n_in,
                              void* d_out, int out_size) {
    const int*   tgt  = (const int*)d_in[0];
    const float* ctx  = (const float*)d_in[1];
    const float* h0   = (const float*)d_in[2];
    const float* emb  = (const float*)d_in[3];
    const float* Wc   = (const float*)d_in[4];
    const float* Wq   = (const float*)d_in[5];
    const float* bq   = (const float*)d_in[6];
    const float* v    = (const float*)d_in[7];
    const float* W_ih = (const float*)d_in[8];
    const float* W_hh = (const float*)d_in[9];
    const float* b_ih = (const float*)d_in[10];
    const float* b_hh = (const float*)d_in[11];
    float* out = (float*)d_out;

    float *p_cp, *p_ge, *p_cr, *p_wcr, *p_xe, *p_wihe;
    cudaGetSymbolAddress((void**)&p_cp,   g_ctxproj);
    cudaGetSymbolAddress((void**)&p_ge,   g_giemb);
    cudaGetSymbolAddress((void**)&p_cr,   g_ctxr);
    cudaGetSymbolAddress((void**)&p_wcr,  g_Wcr);
    cudaGetSymbolAddress((void**)&p_xe,   g_xemb);
    cudaGetSymbolAddress((void**)&p_wihe, g_Wihe);

    k_prep<<<1024, 256>>>(h0, Wq, W_hh, W_ih, Wc, ctx);
    k_emb<<<B * S, 128>>>(tgt, emb, out);

    // ctx_proj[B*L, H] = ctxR @ WcR^T
    gemm_pre2<<<dim3(H / 128, (B * L) / 64), 256>>>(p_cr, CDIM, p_wcr, CDIM, p_cp, H, 64);
    // bf16 copy of ctx_proj for the scores path
    k_cvt_bf<<<1024, 256>>>();
    // gi_emb[B*S, 3H] = embR @ WiheR^T
    gemm_pre2<<<dim3(G3 / 128, (B * S) / 64), 256>>>(p_xe, E, p_wihe, E, p_ge, G3, 16);

    for (int t = 0; t < S; t++) {
        launch_pdl(kA, dim3(192), dim3(1024), ctx, bq, v, out, t);
        launch_pdl(kB, dim3(544), dim3(256), b_ih, b_hh, out, t);
    }
}